// round 2
// baseline (speedup 1.0000x reference)
#include <cuda_runtime.h>
#include <math.h>

// Problem constants
#define BB 4
#define CC 16
#define HH 384
#define WW 384
#define HW (HH*WW)
#define NPTS 384
#define NUM_ITER 20

// ---------------- device scratch (static __device__ arrays; no allocation) ---------
__device__ float2 g_K[BB*CC*HH*WW];   // per-coil k-space / row-transform scratch (~75.5 MB)
__device__ float2 g_y[BB*HH*WW];      // FISTA y
__device__ float2 g_Ab[BB*HH*WW];     // A_adj(b) precompute (also used as temp U)

// ---------------- complex helpers ---------------------------------------------------
__device__ __forceinline__ float2 cmul(float2 a, float2 b) {
    return make_float2(fmaf(a.x, b.x, -a.y * b.y), fmaf(a.x, b.y, a.y * b.x));
}
__device__ __forceinline__ float2 cadd(float2 a, float2 b) { return make_float2(a.x+b.x, a.y+b.y); }
__device__ __forceinline__ float2 csub(float2 a, float2 b) { return make_float2(a.x-b.x, a.y-b.y); }

// Build twiddle table tw[t] = exp(-2*pi*i*t/384)
template<int NTHR>
__device__ __forceinline__ void build_tw(float2* tw, int tid) {
    for (int t = tid; t < NPTS; t += NTHR) {
        float s, c;
        sincospif(-2.0f * (float)t / (float)NPTS, &s, &c);
        tw[t] = make_float2(c, s);
    }
}

// ============ 384-point FFT, 64 threads, stride-1 layout =====================
// Input: natural order in A. Output: natural order in A's buddy (returned in A).
// Decomposition 384 = 3 x 128: three decimated 128-pt Stockham FFTs, radix-3 combine.
// Requires __syncthreads() BEFORE call (A fully written). No trailing sync:
// afterwards thread t owns A[t + 64*u], u = 0..5.
template<bool INV>
__device__ void fft384_64(float2* A, float2* Bb, const float2* tw, int t) {
    float2* src = A;
    float2* dst = Bb;
    #pragma unroll
    for (int s = 0; s < 7; s++) {
        const int m  = 1 << s;
        const int jm = (t >> s) << s;     // floor(j/m)*m
        float2 w = tw[3 * jm];            // W_128^jm
        if (INV) w.y = -w.y;
        #pragma unroll
        for (int f = 0; f < 3; f++) {
            float2 a, b;
            if (s == 0) {               // gather decimation x[3*n2 + f]
                a = src[3*t + f];
                b = src[3*t + 192 + f];
            } else {
                a = src[f*128 + t];
                b = src[f*128 + t + 64];
            }
            float2 sum = cadd(a, b);
            float2 dif = csub(a, b);
            const int base = f*128 + t + jm;
            dst[base]     = sum;
            dst[base + m] = cmul(w, dif);
        }
        __syncthreads();
        float2* tmp = src; src = dst; dst = tmp;
    }
    // 7 stages (odd): src == Bb holds Y_f[k2] at [f*128+k2]; combine into A.
    #pragma unroll
    for (int u = 0; u < 6; u++) {
        const int k  = t + 64*u;
        const int k2 = k & 127;
        float2 y0 = src[k2];
        float2 y1 = src[128 + k2];
        float2 y2 = src[256 + k2];
        int e2 = 2*k; if (e2 >= NPTS) e2 -= NPTS;
        float2 w1 = tw[k], w2 = tw[e2];
        if (INV) { w1.y = -w1.y; w2.y = -w2.y; }
        float2 r = cadd(cadd(y0, cmul(w1, y1)), cmul(w2, y2));
        if (INV) { r.x *= (1.0f/384.0f); r.y *= (1.0f/384.0f); }
        dst[k] = r;
    }
}

// ============ batched 384-pt FFT over 16 columns, NT threads ==================
// tile layout: T[h*16 + col]. Transform along h for each of 16 columns.
// Trailing __syncthreads included (callers touch arbitrary elements after).
template<bool INV, int NT>
__device__ void fft384_b16(float2* A, float2* Bb, const float2* tw, int tid) {
    const int col   = tid & 15;
    const int lane  = tid >> 4;           // 0..NT/16-1
    const int LANES = NT / 16;
    float2* src = A;
    float2* dst = Bb;
    #pragma unroll
    for (int s = 0; s < 7; s++) {
        const int m = 1 << s;
        #pragma unroll
        for (int idx = lane; idx < 192; idx += LANES) {   // 192 butterflies
            const int f = idx >> 6;
            const int j = idx & 63;
            const int jm = (j >> s) << s;
            float2 w = tw[3 * jm];
            if (INV) w.y = -w.y;
            float2 a, b;
            if (s == 0) {
                a = src[(3*j + f)*16 + col];
                b = src[(3*j + 192 + f)*16 + col];
            } else {
                a = src[(f*128 + j)*16 + col];
                b = src[(f*128 + j + 64)*16 + col];
            }
            float2 sum = cadd(a, b);
            float2 dif = csub(a, b);
            const int base = (f*128 + j + jm)*16 + col;
            dst[base]        = sum;
            dst[base + m*16] = cmul(w, dif);
        }
        __syncthreads();
        float2* tmp = src; src = dst; dst = tmp;
    }
    #pragma unroll
    for (int k = lane; k < NPTS; k += LANES) {
        const int k2 = k & 127;
        float2 y0 = src[k2*16 + col];
        float2 y1 = src[(128 + k2)*16 + col];
        float2 y2 = src[(256 + k2)*16 + col];
        int e2 = 2*k; if (e2 >= NPTS) e2 -= NPTS;
        float2 w1 = tw[k], w2 = tw[e2];
        if (INV) { w1.y = -w1.y; w2.y = -w2.y; }
        float2 r = cadd(cadd(y0, cmul(w1, y1)), cmul(w2, y2));
        if (INV) { r.x *= (1.0f/384.0f); r.y *= (1.0f/384.0f); }
        dst[k*16 + col] = r;
    }
    __syncthreads();
}

#define GCOL_NT 512

// ================= gcol: column FFT -> (mask) -> column IFFT, in place =======
// which==0: operate on g_K (64 images), apply mask (full fwd+mask+inv round trip)
// which==1: operate on g_Ab (4 images), inverse only, no mask
extern "C" __global__ void __launch_bounds__(GCOL_NT)
gcol_kernel(int which, const int* __restrict__ mask) {
    extern __shared__ float2 sm[];
    float2* A  = sm;                // 384*16
    float2* Bb = sm + NPTS*16;      // 384*16
    __shared__ float2 tw[NPTS];
    const int tid = threadIdx.x;
    build_tw<GCOL_NT>(tw, tid);

    const int img = blockIdx.y;
    const int w0  = blockIdx.x * 16;
    float2* g = (which ? g_Ab : g_K) + (size_t)img * HW;

    for (int idx = tid; idx < NPTS*16; idx += GCOL_NT) {
        const int h = idx >> 4, cl = idx & 15;
        A[idx] = g[h*WW + w0 + cl];
    }
    __syncthreads();

    if (which == 0) {
        fft384_b16<false, GCOL_NT>(A, Bb, tw, tid);      // ends natural order in A
        const int b = img >> 4;
        const int* mrow = mask + (size_t)b * HW;
        for (int idx = tid; idx < NPTS*16; idx += GCOL_NT) {
            const int h = idx >> 4, cl = idx & 15;
            const int mv = mrow[h*WW + w0 + cl];
            float2 v = A[idx];
            A[idx] = mv ? v : make_float2(0.f, 0.f);
        }
        __syncthreads();
        fft384_b16<true, GCOL_NT>(A, Bb, tw, tid);
    } else {
        fft384_b16<true, GCOL_NT>(A, Bb, tw, tid);
    }

    for (int idx = tid; idx < NPTS*16; idx += GCOL_NT) {
        const int h = idx >> 4, cl = idx & 15;
        g[h*WW + w0 + cl] = A[idx];
    }
}

// ================= fused per-row kernel =======================================
// do_adj: row-IFFT 16 coil rows of g_K, accumulate conj(coil)*v, FISTA update
//         (x in d_out planes, y in g_y). Else: load y row directly.
// do_fwd: row-FFT of coil_c * y_new back into the same g_K rows.
extern "C" __global__ void __launch_bounds__(64)
f_kernel(const float* __restrict__ csm, const float* __restrict__ z_k,
         const float* __restrict__ lam_p, float* __restrict__ out,
         float alpha, int do_adj, int do_fwd) {
    __shared__ float2 A[NPTS], Bb[NPTS], tw[NPTS];
    const int t = threadIdx.x;
    const int h = blockIdx.x;
    const int b = blockIdx.y;
    build_tw<64>(tw, t);
    __syncthreads();

    float2 ynreg[6];

    if (do_adj) {
        float2 acc[6];
        #pragma unroll
        for (int u = 0; u < 6; u++) acc[u] = make_float2(0.f, 0.f);

        for (int c = 0; c < CC; c++) {
            const float2* krow = g_K + ((size_t)(b*CC + c)*HH + h) * WW;
            #pragma unroll
            for (int u = 0; u < 6; u++) A[t + 64*u] = krow[t + 64*u];
            __syncthreads();
            fft384_64<true>(A, Bb, tw, t);
            const float* cre = csm + ((size_t)((b*2 + 0)*CC + c)*HH + h) * WW;
            const float* cim = csm + ((size_t)((b*2 + 1)*CC + c)*HH + h) * WW;
            #pragma unroll
            for (int u = 0; u < 6; u++) {
                const int w = t + 64*u;
                const float sr = cre[w], si = cim[w];
                const float2 v = A[w];
                // conj(s) * v
                acc[u].x = fmaf(sr, v.x, fmaf( si, v.y, acc[u].x));
                acc[u].y = fmaf(sr, v.y, fmaf(-si, v.x, acc[u].y));
            }
        }

        const float lam = lam_p[0];
        const float2* abrow = g_Ab + ((size_t)b*HH + h) * WW;
        float2* yrow = g_y + ((size_t)b*HH + h) * WW;
        float* xre = out + ((size_t)(b*2 + 0)*HH + h) * WW;
        float* xim = out + ((size_t)(b*2 + 1)*HH + h) * WW;
        const float* zre = z_k + ((size_t)(b*2 + 0)*HH + h) * WW;
        const float* zim = z_k + ((size_t)(b*2 + 1)*HH + h) * WW;

        #pragma unroll
        for (int u = 0; u < 6; u++) {
            const int w = t + 64*u;
            const float2 ab = abrow[w];
            const float gx = acc[u].x - ab.x;
            const float gy = acc[u].y - ab.y;
            const float2 yv = yrow[w];
            float xnr = yv.x - gx;
            float xni = yv.y - gy;
            xnr = xnr - lam * (xnr - zre[w]);
            xni = xni - lam * (xni - zim[w]);
            xnr = fmaxf(xnr, 0.f);
            xni = fmaxf(xni, 0.f);
            const float xor_ = xre[w], xoi = xim[w];
            const float ynr = xnr + alpha * (xnr - xor_);
            const float yni = xni + alpha * (xni - xoi);
            xre[w] = xnr; xim[w] = xni;
            yrow[w] = make_float2(ynr, yni);
            ynreg[u] = make_float2(ynr, yni);
        }
    } else {
        const float2* yrow = g_y + ((size_t)b*HH + h) * WW;
        #pragma unroll
        for (int u = 0; u < 6; u++) ynreg[u] = yrow[t + 64*u];
    }

    if (do_fwd) {
        for (int c = 0; c < CC; c++) {
            const float* cre = csm + ((size_t)((b*2 + 0)*CC + c)*HH + h) * WW;
            const float* cim = csm + ((size_t)((b*2 + 1)*CC + c)*HH + h) * WW;
            #pragma unroll
            for (int u = 0; u < 6; u++) {
                const int w = t + 64*u;
                A[w] = cmul(make_float2(cre[w], cim[w]), ynreg[u]);
            }
            __syncthreads();
            fft384_64<false>(A, Bb, tw, t);
            float2* krow = g_K + ((size_t)(b*CC + c)*HH + h) * WW;
            #pragma unroll
            for (int u = 0; u < 6; u++) krow[t + 64*u] = A[t + 64*u];
        }
    }
}

// ============ prologue: row inverse FFT of mask*b into g_Ab (as U) ===========
extern "C" __global__ void __launch_bounds__(64)
pmaskrow_kernel(const float* __restrict__ x0, const int* __restrict__ mask) {
    __shared__ float2 A[NPTS], Bb[NPTS], tw[NPTS];
    const int t = threadIdx.x;
    const int h = blockIdx.x;
    const int b = blockIdx.y;
    build_tw<64>(tw, t);
    const float* br = x0 + ((size_t)(b*2 + 0)*HH + h) * WW;
    const float* bi = x0 + ((size_t)(b*2 + 1)*HH + h) * WW;
    const int* mrow = mask + ((size_t)b*HH + h) * WW;
    #pragma unroll
    for (int u = 0; u < 6; u++) {
        const int w = t + 64*u;
        A[w] = mrow[w] ? make_float2(br[w], bi[w]) : make_float2(0.f, 0.f);
    }
    __syncthreads();
    fft384_64<true>(A, Bb, tw, t);
    float2* urow = g_Ab + ((size_t)b*HH + h) * WW;
    #pragma unroll
    for (int u = 0; u < 6; u++) urow[t + 64*u] = A[t + 64*u];
}

// ============ prologue: Ab = (sum_c conj(coil_c)) * U  (pointwise) ===========
extern "C" __global__ void __launch_bounds__(256)
pab_kernel(const float* __restrict__ csm) {
    const int p = blockIdx.x * 256 + threadIdx.x;
    if (p >= BB*HW) return;
    const int b = p / HW;
    const int r = p - b * HW;
    float sr = 0.f, si = 0.f;
    #pragma unroll
    for (int c = 0; c < CC; c++) {
        sr += csm[((size_t)((b*2 + 0)*CC + c))*HW + r];
        si += csm[((size_t)((b*2 + 1)*CC + c))*HW + r];
    }
    const float2 u = g_Ab[p];
    // conj(cs) * u
    g_Ab[p] = make_float2(fmaf(sr, u.x,  si*u.y), fmaf(sr, u.y, -si*u.x));
}

// ============ prologue: iteration 0 pointwise (y=0 case) =====================
// x1 = relu((1-lam)*Ab + lam*zc);  y1 = x1  (alpha_0 = 0)
extern "C" __global__ void __launch_bounds__(256)
p2_kernel(const float* __restrict__ z_k, const float* __restrict__ lam_p,
          float* __restrict__ out) {
    const int p = blockIdx.x * 256 + threadIdx.x;
    if (p >= BB*HW) return;
    const int b = p / HW;
    const int r = p - b * HW;
    const float lam = lam_p[0];
    const float2 ab = g_Ab[p];
    const float zr = z_k[((size_t)(b*2 + 0))*HW + r];
    const float zi = z_k[((size_t)(b*2 + 1))*HW + r];
    float xr = (1.f - lam) * ab.x + lam * zr;
    float xi = (1.f - lam) * ab.y + lam * zi;
    xr = fmaxf(xr, 0.f);
    xi = fmaxf(xi, 0.f);
    out[((size_t)(b*2 + 0))*HW + r] = xr;
    out[((size_t)(b*2 + 1))*HW + r] = xi;
    g_y[p] = make_float2(xr, xi);
}

// ================================ host ========================================
extern "C" void kernel_launch(void* const* d_in, const int* in_sizes, int n_in,
                              void* d_out, int out_size) {
    const float* z_k  = (const float*)d_in[0];
    const float* x0   = (const float*)d_in[1];
    const float* csm  = (const float*)d_in[2];
    const float* lam  = (const float*)d_in[3];
    const int*   mask = (const int*)d_in[4];
    float* out = (float*)d_out;

    const size_t GSM = 2 * (size_t)NPTS * 16 * sizeof(float2);  // 98304 B
    cudaFuncSetAttribute((const void*)gcol_kernel,
                         cudaFuncAttributeMaxDynamicSharedMemorySize, (int)GSM);

    // FISTA momentum coefficients alpha_i = (t_i - 1)/t_{i+1}, t_0 = 1 (fp32 like ref)
    float alphas[NUM_ITER];
    float tcur = 1.0f;
    for (int i = 0; i < NUM_ITER; i++) {
        const float tn = (1.0f + sqrtf(1.0f + 4.0f * tcur * tcur)) * 0.5f;
        alphas[i] = (tcur - 1.0f) / tn;
        tcur = tn;
    }

    const int npix_blocks = (BB*HW + 255) / 256;

    // --- prologue: Ab = (sum_c conj coil) * ifft2(mask * b)
    pmaskrow_kernel<<<dim3(HH, BB), 64>>>(x0, mask);
    gcol_kernel<<<dim3(WW/16, BB), GCOL_NT, GSM>>>(1, nullptr);
    pab_kernel<<<npix_blocks, 256>>>(csm);

    // --- iteration 0 (y = 0): pure pointwise
    p2_kernel<<<npix_blocks, 256>>>(z_k, lam, out);

    // --- initial forward row FFTs of coil * y1
    f_kernel<<<dim3(HH, BB), 64>>>(csm, z_k, lam, out, 0.0f, 0, 1);

    // --- iterations 1..19
    for (int i = 1; i < NUM_ITER; i++) {
        gcol_kernel<<<dim3(WW/16, BB*CC), GCOL_NT, GSM>>>(0, mask);
        const int do_fwd = (i < NUM_ITER - 1) ? 1 : 0;
        f_kernel<<<dim3(HH, BB), 64>>>(csm, z_k, lam, out, alphas[i], 1, do_fwd);
    }
}

// round 3
// speedup vs baseline: 1.3847x; 1.3847x over previous
#include <cuda_runtime.h>
#include <math.h>

// Problem constants
#define BB 4
#define CC 16
#define HH 384
#define WW 384
#define HW (HH*WW)
#define NPTS 384
#define NUM_ITER 20

// ---------------- device scratch (static __device__ arrays; no allocation) ---------
__device__ float2 g_K[BB*CC*HH*WW];   // per-coil k-space scratch (~75.5 MB)
__device__ float2 g_y[BB*HH*WW];      // FISTA y
__device__ float2 g_Ab[BB*HH*WW];     // A_adj(b) precompute (also temp U)

// ---------------- complex helpers ---------------------------------------------------
__device__ __forceinline__ float2 cmul(float2 a, float2 b) {
    return make_float2(fmaf(a.x, b.x, -a.y * b.y), fmaf(a.x, b.y, a.y * b.x));
}
__device__ __forceinline__ float2 cadd(float2 a, float2 b) { return make_float2(a.x+b.x, a.y+b.y); }
__device__ __forceinline__ float2 csub(float2 a, float2 b) { return make_float2(a.x-b.x, a.y-b.y); }

// radix-4 butterfly: y_k = W^{jm*k} * sum_q x_q * omega4^{qk}   (omega4 = -i fwd, +i inv)
template<bool INV>
__device__ __forceinline__ void bf4(float2 x0, float2 x1, float2 x2, float2 x3,
                                    float2 w1, float2 w2, float2 w3,
                                    float2& y0, float2& y1, float2& y2, float2& y3) {
    float2 s02 = cadd(x0, x2), d02 = csub(x0, x2);
    float2 s13 = cadd(x1, x3), d13 = csub(x1, x3);
    float2 jd13 = INV ? make_float2(-d13.y, d13.x) : make_float2(d13.y, -d13.x);
    y0 = cadd(s02, s13);
    y1 = cmul(w1, cadd(d02, jd13));
    y2 = cmul(w2, csub(s02, s13));
    y3 = cmul(w3, csub(d02, jd13));
}

// twiddle table tw[t] = exp(-2*pi*i*t/384)
template<int NTHR>
__device__ __forceinline__ void build_tw(float2* tw, int tid) {
    for (int t = tid; t < NPTS; t += NTHR) {
        float s, c;
        sincospif(-2.0f * (float)t / (float)NPTS, &s, &c);
        tw[t] = make_float2(c, s);
    }
}

// ============ 384-pt FFT, 64-thread group, stride-1, mixed radix 4*4*4*2 + r3 =======
// Input: natural order in A (sync'd before call). Uses block-wide __syncthreads:
// ALL groups in the block must call in lockstep. Returns pointer to result buffer
// (natural order). NO trailing sync: thread t may immediately read res[t+64u] (it
// wrote those itself in the combine). Any other access (incl. refilling A) needs a
// caller-side __syncthreads first.
template<bool INV>
__device__ float2* fft384_r4(float2* A, float2* Bb, const float2* tw, int t) {
    float2* src = A;
    float2* dst = Bb;
    // three radix-4 stages: m = 1, 4, 16  (96 butterflies each over 3x128 blocks)
    #pragma unroll
    for (int s = 0; s < 3; s++) {
        const int m = 1 << (2*s);
        #pragma unroll
        for (int idx = t; idx < 96; idx += 64) {
            const int f = idx >> 5;
            const int j = idx & 31;
            const int jm = (j >> (2*s)) << (2*s);
            float2 w1 = tw[3*jm], w2 = tw[6*jm], w3 = tw[9*jm];
            if (INV) { w1.y = -w1.y; w2.y = -w2.y; w3.y = -w3.y; }
            float2 x0, x1, x2, x3;
            if (s == 0) {      // decimated gather x[3n+f]
                x0 = src[3*j + f];       x1 = src[3*j + 96 + f];
                x2 = src[3*j + 192 + f]; x3 = src[3*j + 288 + f];
            } else {
                const int bs = f*128 + j;
                x0 = src[bs]; x1 = src[bs+32]; x2 = src[bs+64]; x3 = src[bs+96];
            }
            float2 y0, y1, y2, y3;
            bf4<INV>(x0, x1, x2, x3, w1, w2, w3, y0, y1, y2, y3);
            const int base = f*128 + j + 3*jm;
            dst[base]       = y0;
            dst[base + m]   = y1;
            dst[base + 2*m] = y2;
            dst[base + 3*m] = y3;
        }
        __syncthreads();
        float2* tmp = src; src = dst; dst = tmp;
    }
    // radix-2 final stage (m=64, trivial twiddles), 192 butterflies
    #pragma unroll
    for (int idx = t; idx < 192; idx += 64) {
        const int f = idx >> 6;
        const int j = idx & 63;
        const int bs = f*128 + j;
        float2 a = src[bs], b = src[bs + 64];
        dst[bs]      = cadd(a, b);
        dst[bs + 64] = csub(a, b);
    }
    __syncthreads();
    { float2* tmp = src; src = dst; dst = tmp; }
    // radix-3 combine: X[k] = Y0[k2] + W^k Y1[k2] + W^{2k} Y2[k2]
    #pragma unroll
    for (int u = 0; u < 6; u++) {
        const int k  = t + 64*u;
        const int k2 = k & 127;
        float2 y0 = src[k2], y1 = src[128 + k2], y2 = src[256 + k2];
        int e2 = 2*k; if (e2 >= NPTS) e2 -= NPTS;
        float2 w1 = tw[k], w2 = tw[e2];
        if (INV) { w1.y = -w1.y; w2.y = -w2.y; }
        float2 r = cadd(cadd(y0, cmul(w1, y1)), cmul(w2, y2));
        if (INV) { r.x *= (1.0f/384.0f); r.y *= (1.0f/384.0f); }
        dst[k] = r;
    }
    return dst;
}

// ============ batched 384-pt FFT over 16 columns, NT threads, radix 4*4*4*2 + r3 ====
// tile layout T[pos*16 + col]. Returns pointer to result buffer. Trailing sync
// INCLUDED (callers touch arbitrary elements after).
template<bool INV, int NT>
__device__ float2* fft384_b16r4(float2* in, float2* tmp, const float2* tw, int tid) {
    const int col   = tid & 15;
    const int lane  = tid >> 4;
    const int LANES = NT / 16;
    float2* src = in;
    float2* dst = tmp;
    #pragma unroll
    for (int s = 0; s < 3; s++) {
        const int m = 1 << (2*s);
        #pragma unroll
        for (int idx = lane; idx < 96; idx += LANES) {
            const int f = idx >> 5;
            const int j = idx & 31;
            const int jm = (j >> (2*s)) << (2*s);
            float2 w1 = tw[3*jm], w2 = tw[6*jm], w3 = tw[9*jm];
            if (INV) { w1.y = -w1.y; w2.y = -w2.y; w3.y = -w3.y; }
            float2 x0, x1, x2, x3;
            if (s == 0) {
                x0 = src[(3*j + f)*16 + col];       x1 = src[(3*j + 96 + f)*16 + col];
                x2 = src[(3*j + 192 + f)*16 + col]; x3 = src[(3*j + 288 + f)*16 + col];
            } else {
                const int bs = f*128 + j;
                x0 = src[bs*16 + col];      x1 = src[(bs+32)*16 + col];
                x2 = src[(bs+64)*16 + col]; x3 = src[(bs+96)*16 + col];
            }
            float2 y0, y1, y2, y3;
            bf4<INV>(x0, x1, x2, x3, w1, w2, w3, y0, y1, y2, y3);
            const int base = f*128 + j + 3*jm;
            dst[base*16 + col]         = y0;
            dst[(base + m)*16 + col]   = y1;
            dst[(base + 2*m)*16 + col] = y2;
            dst[(base + 3*m)*16 + col] = y3;
        }
        __syncthreads();
        float2* t2 = src; src = dst; dst = t2;
    }
    #pragma unroll
    for (int idx = lane; idx < 192; idx += LANES) {
        const int f = idx >> 6;
        const int j = idx & 63;
        const int bs = f*128 + j;
        float2 a = src[bs*16 + col], b = src[(bs+64)*16 + col];
        dst[bs*16 + col]      = cadd(a, b);
        dst[(bs+64)*16 + col] = csub(a, b);
    }
    __syncthreads();
    { float2* t2 = src; src = dst; dst = t2; }
    #pragma unroll
    for (int k = lane; k < NPTS; k += LANES) {
        const int k2 = k & 127;
        float2 y0 = src[k2*16 + col];
        float2 y1 = src[(128 + k2)*16 + col];
        float2 y2 = src[(256 + k2)*16 + col];
        int e2 = 2*k; if (e2 >= NPTS) e2 -= NPTS;
        float2 w1 = tw[k], w2 = tw[e2];
        if (INV) { w1.y = -w1.y; w2.y = -w2.y; }
        float2 r = cadd(cadd(y0, cmul(w1, y1)), cmul(w2, y2));
        if (INV) { r.x *= (1.0f/384.0f); r.y *= (1.0f/384.0f); }
        dst[k*16 + col] = r;
    }
    __syncthreads();
    return dst;
}

#define GCOL_NT 512

// ================= gcol: column FFT -> (mask) -> column IFFT, in place =======
extern "C" __global__ void __launch_bounds__(GCOL_NT)
gcol_kernel(int which, const int* __restrict__ mask) {
    extern __shared__ float2 sm[];
    float2* A  = sm;                 // 384*16
    float2* Bb = sm + NPTS*16;       // 384*16
    __shared__ float2 tw[NPTS];
    const int tid = threadIdx.x;
    build_tw<GCOL_NT>(tw, tid);

    const int img = blockIdx.y;
    const int w0  = blockIdx.x * 16;
    float2* g = (which ? g_Ab : g_K) + (size_t)img * HW;

    for (int idx = tid; idx < NPTS*16; idx += GCOL_NT) {
        const int h = idx >> 4, cl = idx & 15;
        A[idx] = g[h*WW + w0 + cl];
    }
    __syncthreads();

    float2* res;
    if (which == 0) {
        float2* r1 = fft384_b16r4<false, GCOL_NT>(A, Bb, tw, tid);
        const int b = img >> 4;
        const int* mrow = mask + (size_t)b * HW;
        for (int idx = tid; idx < NPTS*16; idx += GCOL_NT) {
            const int h = idx >> 4, cl = idx & 15;
            const int mv = mrow[h*WW + w0 + cl];
            float2 v = r1[idx];
            r1[idx] = mv ? v : make_float2(0.f, 0.f);
        }
        __syncthreads();
        float2* other = (r1 == A) ? Bb : A;
        res = fft384_b16r4<true, GCOL_NT>(r1, other, tw, tid);
    } else {
        res = fft384_b16r4<true, GCOL_NT>(A, Bb, tw, tid);
    }

    for (int idx = tid; idx < NPTS*16; idx += GCOL_NT) {
        const int h = idx >> 4, cl = idx & 15;
        g[h*WW + w0 + cl] = res[idx];
    }
}

// ================= fused per-row kernel: 8 groups x 64 threads ================
// groups g=0..7 each own coils 2g, 2g+1. All groups execute the FFT machinery in
// lockstep so block-wide __syncthreads inside fft384_r4 is uniform.
// dyn smem layout (float2 units): tw[384] | yrow[384] | GA[8][384] | GB[8][384]
#define FNT 512
#define F_SMEM ((768 + 16*NPTS) * (int)sizeof(float2))   // 55296 B

extern "C" __global__ void __launch_bounds__(FNT)
f_kernel(const float* __restrict__ csm, const float* __restrict__ z_k,
         const float* __restrict__ lam_p, float* __restrict__ out,
         float alpha, int do_adj, int do_fwd) {
    extern __shared__ float2 fsm[];
    float2* tw   = fsm;
    float2* yrow = fsm + NPTS;
    const int tid = threadIdx.x;
    const int g   = tid >> 6;
    const int t   = tid & 63;
    float2* GA = fsm + 2*NPTS + g*NPTS;
    float2* GB = fsm + 2*NPTS + 8*NPTS + g*NPTS;
    const int h = blockIdx.x;
    const int b = blockIdx.y;
    build_tw<FNT>(tw, tid);
    __syncthreads();

    if (do_adj) {
        float2 acc[6];
        #pragma unroll
        for (int u = 0; u < 6; u++) acc[u] = make_float2(0.f, 0.f);

        #pragma unroll
        for (int ci = 0; ci < 2; ci++) {
            const int c = 2*g + ci;
            __syncthreads();   // prior combine readers of GA must finish before refill
            const float2* krow = g_K + ((size_t)(b*CC + c)*HH + h) * WW;
            #pragma unroll
            for (int u = 0; u < 6; u++) GA[t + 64*u] = krow[t + 64*u];
            __syncthreads();
            float2* res = fft384_r4<true>(GA, GB, tw, t);
            const float* cre = csm + ((size_t)((b*2 + 0)*CC + c)*HH + h) * WW;
            const float* cim = csm + ((size_t)((b*2 + 1)*CC + c)*HH + h) * WW;
            #pragma unroll
            for (int u = 0; u < 6; u++) {
                const int w = t + 64*u;
                const float sr = cre[w], si = cim[w];
                const float2 v = res[w];          // own-thread value, no sync needed
                acc[u].x = fmaf(sr, v.x, fmaf( si, v.y, acc[u].x));
                acc[u].y = fmaf(sr, v.y, fmaf(-si, v.x, acc[u].y));
            }
        }

        // cross-group reduction: write partials into each group's GA, then sum
        __syncthreads();       // combine readers of GA done
        #pragma unroll
        for (int u = 0; u < 6; u++) GA[t + 64*u] = acc[u];
        __syncthreads();

        if (tid < NPTS) {
            const int w = tid;
            float2 s = make_float2(0.f, 0.f);
            #pragma unroll
            for (int g2 = 0; g2 < 8; g2++) {
                const float2 p = fsm[2*NPTS + g2*NPTS + w];
                s.x += p.x; s.y += p.y;
            }
            const float lam = lam_p[0];
            const float2 ab = g_Ab[((size_t)b*HH + h)*WW + w];
            const float gx = s.x - ab.x;
            const float gy = s.y - ab.y;
            const float2 yv = g_y[((size_t)b*HH + h)*WW + w];
            float xnr = yv.x - gx;
            float xni = yv.y - gy;
            const float zr = z_k[((size_t)(b*2 + 0)*HH + h)*WW + w];
            const float zi = z_k[((size_t)(b*2 + 1)*HH + h)*WW + w];
            xnr = xnr - lam * (xnr - zr);
            xni = xni - lam * (xni - zi);
            xnr = fmaxf(xnr, 0.f);
            xni = fmaxf(xni, 0.f);
            float* xre = out + ((size_t)(b*2 + 0)*HH + h)*WW;
            float* xim = out + ((size_t)(b*2 + 1)*HH + h)*WW;
            const float xor_ = xre[w], xoi = xim[w];
            const float ynr = xnr + alpha * (xnr - xor_);
            const float yni = xni + alpha * (xni - xoi);
            xre[w] = xnr; xim[w] = xni;
            g_y[((size_t)b*HH + h)*WW + w] = make_float2(ynr, yni);
            yrow[w] = make_float2(ynr, yni);
        }
        __syncthreads();
    } else {
        if (tid < NPTS) yrow[tid] = g_y[((size_t)b*HH + h)*WW + tid];
        __syncthreads();
    }

    if (do_fwd) {
        #pragma unroll
        for (int ci = 0; ci < 2; ci++) {
            const int c = 2*g + ci;
            __syncthreads();   // prior combine readers of GA must finish before refill
            const float* cre = csm + ((size_t)((b*2 + 0)*CC + c)*HH + h) * WW;
            const float* cim = csm + ((size_t)((b*2 + 1)*CC + c)*HH + h) * WW;
            #pragma unroll
            for (int u = 0; u < 6; u++) {
                const int w = t + 64*u;
                GA[w] = cmul(make_float2(cre[w], cim[w]), yrow[w]);
            }
            __syncthreads();
            float2* res = fft384_r4<false>(GA, GB, tw, t);
            float2* krow = g_K + ((size_t)(b*CC + c)*HH + h) * WW;
            #pragma unroll
            for (int u = 0; u < 6; u++) krow[t + 64*u] = res[t + 64*u];
        }
    }
}

// ============ prologue: row inverse FFT of mask*b into g_Ab (as U) ===========
extern "C" __global__ void __launch_bounds__(64)
pmaskrow_kernel(const float* __restrict__ x0, const int* __restrict__ mask) {
    __shared__ float2 A[NPTS], Bb[NPTS], tw[NPTS];
    const int t = threadIdx.x;
    const int h = blockIdx.x;
    const int b = blockIdx.y;
    build_tw<64>(tw, t);
    const float* br = x0 + ((size_t)(b*2 + 0)*HH + h) * WW;
    const float* bi = x0 + ((size_t)(b*2 + 1)*HH + h) * WW;
    const int* mrow = mask + ((size_t)b*HH + h) * WW;
    #pragma unroll
    for (int u = 0; u < 6; u++) {
        const int w = t + 64*u;
        A[w] = mrow[w] ? make_float2(br[w], bi[w]) : make_float2(0.f, 0.f);
    }
    __syncthreads();
    float2* res = fft384_r4<true>(A, Bb, tw, t);
    float2* urow = g_Ab + ((size_t)b*HH + h) * WW;
    #pragma unroll
    for (int u = 0; u < 6; u++) urow[t + 64*u] = res[t + 64*u];
}

// ============ prologue: Ab = (sum_c conj(coil_c)) * U  (pointwise) ===========
extern "C" __global__ void __launch_bounds__(256)
pab_kernel(const float* __restrict__ csm) {
    const int p = blockIdx.x * 256 + threadIdx.x;
    if (p >= BB*HW) return;
    const int b = p / HW;
    const int r = p - b * HW;
    float sr = 0.f, si = 0.f;
    #pragma unroll
    for (int c = 0; c < CC; c++) {
        sr += csm[((size_t)((b*2 + 0)*CC + c))*HW + r];
        si += csm[((size_t)((b*2 + 1)*CC + c))*HW + r];
    }
    const float2 u = g_Ab[p];
    g_Ab[p] = make_float2(fmaf(sr, u.x,  si*u.y), fmaf(sr, u.y, -si*u.x));
}

// ============ prologue: iteration 0 pointwise (y=0 case) =====================
extern "C" __global__ void __launch_bounds__(256)
p2_kernel(const float* __restrict__ z_k, const float* __restrict__ lam_p,
          float* __restrict__ out) {
    const int p = blockIdx.x * 256 + threadIdx.x;
    if (p >= BB*HW) return;
    const int b = p / HW;
    const int r = p - b * HW;
    const float lam = lam_p[0];
    const float2 ab = g_Ab[p];
    const float zr = z_k[((size_t)(b*2 + 0))*HW + r];
    const float zi = z_k[((size_t)(b*2 + 1))*HW + r];
    float xr = (1.f - lam) * ab.x + lam * zr;
    float xi = (1.f - lam) * ab.y + lam * zi;
    xr = fmaxf(xr, 0.f);
    xi = fmaxf(xi, 0.f);
    out[((size_t)(b*2 + 0))*HW + r] = xr;
    out[((size_t)(b*2 + 1))*HW + r] = xi;
    g_y[p] = make_float2(xr, xi);
}

// ================================ host ========================================
extern "C" void kernel_launch(void* const* d_in, const int* in_sizes, int n_in,
                              void* d_out, int out_size) {
    const float* z_k  = (const float*)d_in[0];
    const float* x0   = (const float*)d_in[1];
    const float* csm  = (const float*)d_in[2];
    const float* lam  = (const float*)d_in[3];
    const int*   mask = (const int*)d_in[4];
    float* out = (float*)d_out;

    const size_t GSM = 2 * (size_t)NPTS * 16 * sizeof(float2);  // 98304 B
    cudaFuncSetAttribute((const void*)gcol_kernel,
                         cudaFuncAttributeMaxDynamicSharedMemorySize, (int)GSM);
    cudaFuncSetAttribute((const void*)f_kernel,
                         cudaFuncAttributeMaxDynamicSharedMemorySize, F_SMEM);

    // FISTA momentum coefficients alpha_i = (t_i - 1)/t_{i+1}, t_0 = 1
    float alphas[NUM_ITER];
    float tcur = 1.0f;
    for (int i = 0; i < NUM_ITER; i++) {
        const float tn = (1.0f + sqrtf(1.0f + 4.0f * tcur * tcur)) * 0.5f;
        alphas[i] = (tcur - 1.0f) / tn;
        tcur = tn;
    }

    const int npix_blocks = (BB*HW + 255) / 256;

    // --- prologue: Ab = (sum_c conj coil) * ifft2(mask * b)
    pmaskrow_kernel<<<dim3(HH, BB), 64>>>(x0, mask);
    gcol_kernel<<<dim3(WW/16, BB), GCOL_NT, GSM>>>(1, nullptr);
    pab_kernel<<<npix_blocks, 256>>>(csm);

    // --- iteration 0 (y = 0): pure pointwise
    p2_kernel<<<npix_blocks, 256>>>(z_k, lam, out);

    // --- initial forward row FFTs of coil * y1
    f_kernel<<<dim3(HH, BB), FNT, F_SMEM>>>(csm, z_k, lam, out, 0.0f, 0, 1);

    // --- iterations 1..19
    for (int i = 1; i < NUM_ITER; i++) {
        gcol_kernel<<<dim3(WW/16, BB*CC), GCOL_NT, GSM>>>(0, mask);
        const int do_fwd = (i < NUM_ITER - 1) ? 1 : 0;
        f_kernel<<<dim3(HH, BB), FNT, F_SMEM>>>(csm, z_k, lam, out, alphas[i], 1, do_fwd);
    }
}